// round 1
// baseline (speedup 1.0000x reference)
#include <cuda_runtime.h>

#define BB 4
#define SS 2048
#define DD 500
#define HH 10
#define DHD 50
#define NROWS 8192          // BB*SS
#define NELEM 4096000       // NROWS*DD

// ---------------- scratch (device globals; no allocations allowed) -------------
__device__ float g_q[NELEM];
__device__ float g_k[NELEM];
__device__ float g_v[NELEM];
__device__ float g_out1[NELEM];
__device__ float g_h[NELEM];
__device__ float g_t[NELEM];
__device__ float g_out2[NELEM];
__device__ float g_part[128 * DD];
__device__ float g_partq[128 * DD];
__device__ float g_mu[DD];
__device__ float g_rs[DD];

// ---------------- helpers ------------------------------------------------------
__device__ __forceinline__ float blockReduceSum256(float v) {
  __shared__ float sh[8];
  #pragma unroll
  for (int off = 16; off; off >>= 1) v += __shfl_xor_sync(0xffffffffu, v, off);
  if ((threadIdx.x & 31) == 0) sh[threadIdx.x >> 5] = v;
  __syncthreads();
  if (threadIdx.x < 32) {
    float t = (threadIdx.x < 8) ? sh[threadIdx.x] : 0.f;
    #pragma unroll
    for (int off = 4; off; off >>= 1) t += __shfl_xor_sync(0xffffffffu, t, off);
    if (threadIdx.x == 0) sh[0] = t;
  }
  __syncthreads();
  float r = sh[0];
  __syncthreads();
  return r;
}

// ---------------- kernel 1: LN1 + QKV projection --------------------------------
// 8 rows per block; weights cached in registers per output and reused across rows.
__global__ void __launch_bounds__(256) ln1_qkv_kernel(
    const float* __restrict__ x,
    const float* __restrict__ g, const float* __restrict__ b,
    const float* __restrict__ Wq, const float* __restrict__ bq,
    const float* __restrict__ Wk, const float* __restrict__ bk,
    const float* __restrict__ Wv, const float* __restrict__ bv) {
  __shared__ float xr[8][DD];
  int row0 = blockIdx.x * 8;
  for (int rr = 0; rr < 8; rr++) {
    const float* xp = x + (size_t)(row0 + rr) * DD;
    float s = 0.f;
    for (int d = threadIdx.x; d < DD; d += 256) { float v = xp[d]; xr[rr][d] = v; s += v; }
    s = blockReduceSum256(s);
    float mu = s * (1.f / DD);
    float q = 0.f;
    for (int d = threadIdx.x; d < DD; d += 256) { float t = xr[rr][d] - mu; q += t * t; }
    q = blockReduceSum256(q);
    float rstd = rsqrtf(q * (1.f / DD) + 1e-5f);
    for (int d = threadIdx.x; d < DD; d += 256)
      xr[rr][d] = (xr[rr][d] - mu) * rstd * g[d] + b[d];
  }
  __syncthreads();
  int bidx = row0 / SS;
  int s0 = row0 % SS;
  for (int o = threadIdx.x; o < 1500; o += 256) {
    int mat = (o >= 500) + (o >= 1000);
    int rem = o - mat * 500;
    int h = rem / DHD;
    const float* Wsel = (mat == 0) ? Wq : (mat == 1) ? Wk : Wv;
    const float* bsel = (mat == 0) ? bq : (mat == 1) ? bk : bv;
    float* dst = (mat == 0) ? g_q : (mat == 1) ? g_k : g_v;
    const float* wrow = Wsel + rem * DHD;
    float w[DHD];
    #pragma unroll
    for (int d = 0; d < DHD; d++) w[d] = wrow[d];
    float bias = bsel[rem];
    size_t dbase = (((size_t)bidx * HH + h) * SS + s0) * DHD + (rem % DHD);
    #pragma unroll
    for (int rr = 0; rr < 8; rr++) {
      const float* xp = &xr[rr][h * DHD];
      float acc = bias;
      #pragma unroll
      for (int d = 0; d < DHD; d++) acc = fmaf(xp[d], w[d], acc);
      dst[dbase + (size_t)rr * DHD] = acc;
    }
  }
}

// ---------------- kernel 2: flash attention + residual --------------------------
// BM=BN=64, 256 threads (16x16), 4x4 register tiles, online softmax.
// Smem: Qt[50][66] (k-major), KP[64*66] (Kt aliased with Pt), Vs[64][64].
__global__ void __launch_bounds__(256) attn_kernel(const float* __restrict__ x) {
  __shared__ __align__(16) float Qt[DHD * 66];
  __shared__ __align__(16) float KP[64 * 66];
  __shared__ __align__(16) float Vs[64 * 64];
  int qt = blockIdx.x, bh = blockIdx.y;
  int bidx = bh / HH, h = bh - bidx * HH;
  int tid = threadIdx.x, ty = tid >> 4, tx = tid & 15;
  const float scale = 0.14142135623730951f;  // 1/sqrt(50)
  size_t base = (size_t)bh * SS * DHD;
  const float* qg = g_q + base + (size_t)qt * 64 * DHD;
  for (int idx = tid; idx < 64 * DHD; idx += 256) {
    int r = idx / DHD, d = idx - r * DHD;
    Qt[d * 66 + r] = qg[idx] * scale;
  }
  float m[4], l[4], o[4][4];
  #pragma unroll
  for (int i = 0; i < 4; i++) {
    m[i] = -1e30f; l[i] = 0.f;
    #pragma unroll
    for (int j = 0; j < 4; j++) o[i][j] = 0.f;
  }
  for (int kt = 0; kt < SS / 64; kt++) {
    __syncthreads();  // previous PV reads done (also covers Q-load on first iter)
    const float* kg = g_k + base + (size_t)kt * 64 * DHD;
    const float* vg = g_v + base + (size_t)kt * 64 * DHD;
    for (int idx = tid; idx < 64 * DHD; idx += 256) {
      int r = idx / DHD, d = idx - r * DHD;
      KP[d * 66 + r] = kg[idx];
      Vs[r * 64 + d] = vg[idx];
    }
    for (int idx = tid; idx < 64 * 16; idx += 256) {
      int r = idx >> 4, c = 48 + (idx & 15);
      if (c >= DHD) Vs[r * 64 + c] = 0.f;
    }
    __syncthreads();
    float acc[4][4];
    #pragma unroll
    for (int i = 0; i < 4; i++)
      #pragma unroll
      for (int j = 0; j < 4; j++) acc[i][j] = 0.f;
    #pragma unroll 2
    for (int d = 0; d < DHD; d++) {
      float2 q01 = *(const float2*)&Qt[d * 66 + ty * 4];
      float2 q23 = *(const float2*)&Qt[d * 66 + ty * 4 + 2];
      float2 k01 = *(const float2*)&KP[d * 66 + tx * 4];
      float2 k23 = *(const float2*)&KP[d * 66 + tx * 4 + 2];
      float qv[4] = {q01.x, q01.y, q23.x, q23.y};
      float kv[4] = {k01.x, k01.y, k23.x, k23.y};
      #pragma unroll
      for (int i = 0; i < 4; i++)
        #pragma unroll
        for (int j = 0; j < 4; j++) acc[i][j] = fmaf(qv[i], kv[j], acc[i][j]);
    }
    __syncthreads();  // all Kt reads done before Pt overwrites the same smem
    float pj[4][4];
    #pragma unroll
    for (int i = 0; i < 4; i++) {
      float mx = fmaxf(fmaxf(acc[i][0], acc[i][1]), fmaxf(acc[i][2], acc[i][3]));
      #pragma unroll
      for (int off = 8; off; off >>= 1) mx = fmaxf(mx, __shfl_xor_sync(0xffffffffu, mx, off));
      float mnew = fmaxf(m[i], mx);
      float al = __expf(m[i] - mnew);
      float rs = 0.f;
      #pragma unroll
      for (int j = 0; j < 4; j++) { pj[i][j] = __expf(acc[i][j] - mnew); rs += pj[i][j]; }
      #pragma unroll
      for (int off = 8; off; off >>= 1) rs += __shfl_xor_sync(0xffffffffu, rs, off);
      l[i] = l[i] * al + rs;
      m[i] = mnew;
      #pragma unroll
      for (int j = 0; j < 4; j++) o[i][j] *= al;
    }
    #pragma unroll
    for (int j = 0; j < 4; j++) {
      int c = tx * 4 + j;
      *(float2*)&KP[c * 66 + ty * 4]     = make_float2(pj[0][j], pj[1][j]);
      *(float2*)&KP[c * 66 + ty * 4 + 2] = make_float2(pj[2][j], pj[3][j]);
    }
    __syncthreads();
    #pragma unroll 2
    for (int kk = 0; kk < 64; kk++) {
      float2 p01 = *(const float2*)&KP[kk * 66 + ty * 4];
      float2 p23 = *(const float2*)&KP[kk * 66 + ty * 4 + 2];
      float2 v01 = *(const float2*)&Vs[kk * 64 + tx * 4];
      float2 v23 = *(const float2*)&Vs[kk * 64 + tx * 4 + 2];
      float pv[4] = {p01.x, p01.y, p23.x, p23.y};
      float vv[4] = {v01.x, v01.y, v23.x, v23.y};
      #pragma unroll
      for (int i = 0; i < 4; i++)
        #pragma unroll
        for (int j = 0; j < 4; j++) o[i][j] = fmaf(pv[i], vv[j], o[i][j]);
    }
  }
  #pragma unroll
  for (int i = 0; i < 4; i++) {
    float inv = 1.f / l[i];
    int srow = qt * 64 + ty * 4 + i;
    size_t gb = ((size_t)bidx * SS + srow) * DD + h * DHD;
    #pragma unroll
    for (int j = 0; j < 4; j++) {
      int e = tx * 4 + j;
      if (e < DHD) g_out1[gb + e] = x[gb + e] + o[i][j] * inv;
    }
  }
}

// ---------------- kernel 3: LN2 -------------------------------------------------
__global__ void __launch_bounds__(256) ln2_kernel(const float* __restrict__ g,
                                                  const float* __restrict__ b) {
  __shared__ float xr[DD];
  size_t row = blockIdx.x;
  const float* xp = g_out1 + row * DD;
  float s = 0.f;
  for (int d = threadIdx.x; d < DD; d += 256) { float v = xp[d]; xr[d] = v; s += v; }
  s = blockReduceSum256(s);
  float mu = s * (1.f / DD);
  float q = 0.f;
  for (int d = threadIdx.x; d < DD; d += 256) { float t = xr[d] - mu; q += t * t; }
  q = blockReduceSum256(q);
  float rstd = rsqrtf(q * (1.f / DD) + 1e-5f);
  float* op = g_h + row * DD;
  for (int d = threadIdx.x; d < DD; d += 256) op[d] = (xr[d] - mu) * rstd * g[d] + b[d];
}

// ---------------- kernel 4: GEMM  C = A @ W^T + bias ----------------------------
// A: [8192,500] (layer 0: g_h, layer 1: g_out2), W row-major [500,500]; C = g_t.
__global__ void __launch_bounds__(256) gemm_nt_kernel(
    const float* __restrict__ W, const float* __restrict__ bias, int layer) {
  __shared__ __align__(16) float At[32 * 66];
  __shared__ __align__(16) float Bt[32 * 66];
  const float* A = layer ? g_out2 : g_h;
  int m0 = blockIdx.x * 64, n0 = blockIdx.y * 64;
  int tid = threadIdx.x, ty = tid >> 4, tx = tid & 15;
  float acc[4][4];
  #pragma unroll
  for (int i = 0; i < 4; i++)
    #pragma unroll
    for (int j = 0; j < 4; j++) acc[i][j] = 0.f;
  for (int t = 0; t < 16; t++) {  // ceil(500/32)
    int k0 = t * 32;
    __syncthreads();
    for (int idx = tid; idx < 64 * 32; idx += 256) {
      int r = idx >> 5, kk = idx & 31;
      int k = k0 + kk;
      At[kk * 66 + r] = (k < DD) ? A[(size_t)(m0 + r) * DD + k] : 0.f;
      int c = n0 + r;
      Bt[kk * 66 + r] = (k < DD && c < DD) ? W[(size_t)c * DD + k] : 0.f;
    }
    __syncthreads();
    #pragma unroll 4
    for (int kk = 0; kk < 32; kk++) {
      float2 a01 = *(const float2*)&At[kk * 66 + ty * 4];
      float2 a23 = *(const float2*)&At[kk * 66 + ty * 4 + 2];
      float2 b01 = *(const float2*)&Bt[kk * 66 + tx * 4];
      float2 b23 = *(const float2*)&Bt[kk * 66 + tx * 4 + 2];
      float av[4] = {a01.x, a01.y, a23.x, a23.y};
      float bw[4] = {b01.x, b01.y, b23.x, b23.y};
      #pragma unroll
      for (int i = 0; i < 4; i++)
        #pragma unroll
        for (int j = 0; j < 4; j++) acc[i][j] = fmaf(av[i], bw[j], acc[i][j]);
    }
  }
  #pragma unroll
  for (int i = 0; i < 4; i++) {
    int r = m0 + ty * 4 + i;
    #pragma unroll
    for (int j = 0; j < 4; j++) {
      int c = n0 + tx * 4 + j;
      if (c < DD) g_t[(size_t)r * DD + c] = acc[i][j] + bias[c];
    }
  }
}

// ---------------- kernels 5/6: BN column stats (deterministic 2-stage) ----------
__global__ void __launch_bounds__(256) colstat_part_kernel() {
  int p = blockIdx.x;  // 128 blocks x 64 rows
  const float* base = g_t + (size_t)p * 64 * DD;
  int c = threadIdx.x;
  float s0 = 0.f, q0 = 0.f, s1 = 0.f, q1 = 0.f;
  for (int r = 0; r < 64; r++) {
    float v0 = base[r * DD + c]; s0 += v0; q0 += v0 * v0;
    if (c + 256 < DD) { float v1 = base[r * DD + c + 256]; s1 += v1; q1 += v1 * v1; }
  }
  g_part[p * DD + c] = s0; g_partq[p * DD + c] = q0;
  if (c + 256 < DD) { g_part[p * DD + c + 256] = s1; g_partq[p * DD + c + 256] = q1; }
}

__global__ void colstat_final_kernel() {
  int c = blockIdx.x * 256 + threadIdx.x;
  if (c >= DD) return;
  float s = 0.f, q = 0.f;
  for (int i = 0; i < 128; i++) { s += g_part[i * DD + c]; q += g_partq[i * DD + c]; }
  float mu = s * (1.f / NROWS);
  float var = q * (1.f / NROWS) - mu * mu;
  g_mu[c] = mu;
  g_rs[c] = rsqrtf(var + 1e-5f);
}

// ---------------- kernel 7: BN apply + ReLU + residual --------------------------
__global__ void __launch_bounds__(256) bn_apply_kernel(
    const float* __restrict__ g, const float* __restrict__ b, int layer,
    float* __restrict__ out_ext) {
  int idx = blockIdx.x * 256 + threadIdx.x;
  if (idx >= NELEM) return;
  const float* res = layer ? g_out2 : g_out1;
  float* outp = layer ? out_ext : g_out2;
  int c = idx % DD;
  float v = (g_t[idx] - g_mu[c]) * g_rs[c] * g[c] + b[c];
  outp[idx] = res[idx] + fmaxf(v, 0.f);
}

// ---------------- launch --------------------------------------------------------
extern "C" void kernel_launch(void* const* d_in, const int* in_sizes, int n_in,
                              void* d_out, int out_size) {
  (void)in_sizes; (void)n_in; (void)out_size;
  const float* x    = (const float*)d_in[0];
  const float* ln1g = (const float*)d_in[1];
  const float* ln1b = (const float*)d_in[2];
  const float* Wq   = (const float*)d_in[3];
  const float* bq   = (const float*)d_in[4];
  const float* Wk   = (const float*)d_in[5];
  const float* bk   = (const float*)d_in[6];
  const float* Wv   = (const float*)d_in[7];
  const float* bv   = (const float*)d_in[8];
  const float* ln2g = (const float*)d_in[9];
  const float* ln2b = (const float*)d_in[10];
  const float* W1   = (const float*)d_in[11];
  const float* b1   = (const float*)d_in[12];
  const float* bn1g = (const float*)d_in[13];
  const float* bn1b = (const float*)d_in[14];
  const float* W2   = (const float*)d_in[15];
  const float* b2   = (const float*)d_in[16];
  const float* bn2g = (const float*)d_in[17];
  const float* bn2b = (const float*)d_in[18];
  float* out = (float*)d_out;

  ln1_qkv_kernel<<<NROWS / 8, 256>>>(x, ln1g, ln1b, Wq, bq, Wk, bk, Wv, bv);
  attn_kernel<<<dim3(SS / 64, BB * HH), 256>>>(x);
  ln2_kernel<<<NROWS, 256>>>(ln2g, ln2b);
  gemm_nt_kernel<<<dim3(NROWS / 64, 8), 256>>>(W1, b1, 0);
  colstat_part_kernel<<<128, 256>>>();
  colstat_final_kernel<<<2, 256>>>();
  bn_apply_kernel<<<(NELEM + 255) / 256, 256>>>(bn1g, bn1b, 0, out);
  gemm_nt_kernel<<<dim3(NROWS / 64, 8), 256>>>(W2, b2, 1);
  colstat_part_kernel<<<128, 256>>>();
  colstat_final_kernel<<<2, 256>>>();
  bn_apply_kernel<<<(NELEM + 255) / 256, 256>>>(bn2g, bn2b, 1, out);
}

// round 2
// speedup vs baseline: 1.0007x; 1.0007x over previous
#include <cuda_runtime.h>

#define BB 4
#define SS 2048
#define DD 500
#define HH 10
#define DHD 50
#define NROWS 8192          // BB*SS
#define NELEM 4096000       // NROWS*DD

// ---------------- scratch (device globals; no allocations allowed) -------------
__device__ float g_q[NELEM];
__device__ float g_k[NELEM];
__device__ float g_v[NELEM];
__device__ float g_out1[NELEM];
__device__ float g_h[NELEM];
__device__ float g_t[NELEM];
__device__ float g_out2[NELEM];
__device__ float g_part[128 * DD];
__device__ float g_partq[128 * DD];
__device__ float g_mu[DD];
__device__ float g_rs[DD];

// ---------------- helpers ------------------------------------------------------
__device__ __forceinline__ float blockReduceSum256(float v) {
  __shared__ float sh[8];
  #pragma unroll
  for (int off = 16; off; off >>= 1) v += __shfl_xor_sync(0xffffffffu, v, off);
  if ((threadIdx.x & 31) == 0) sh[threadIdx.x >> 5] = v;
  __syncthreads();
  if (threadIdx.x < 32) {
    float t = (threadIdx.x < 8) ? sh[threadIdx.x] : 0.f;
    #pragma unroll
    for (int off = 4; off; off >>= 1) t += __shfl_xor_sync(0xffffffffu, t, off);
    if (threadIdx.x == 0) sh[0] = t;
  }
  __syncthreads();
  float r = sh[0];
  __syncthreads();
  return r;
}

// ---------------- kernel 1: LN1 + QKV projection --------------------------------
// 8 rows per block; weights cached in registers per output and reused across rows.
__global__ void __launch_bounds__(256) ln1_qkv_kernel(
    const float* __restrict__ x,
    const float* __restrict__ g, const float* __restrict__ b,
    const float* __restrict__ Wq, const float* __restrict__ bq,
    const float* __restrict__ Wk, const float* __restrict__ bk,
    const float* __restrict__ Wv, const float* __restrict__ bv) {
  __shared__ float xr[8][DD];
  int row0 = blockIdx.x * 8;
  for (int rr = 0; rr < 8; rr++) {
    const float* xp = x + (size_t)(row0 + rr) * DD;
    float s = 0.f;
    for (int d = threadIdx.x; d < DD; d += 256) { float v = xp[d]; xr[rr][d] = v; s += v; }
    s = blockReduceSum256(s);
    float mu = s * (1.f / DD);
    float q = 0.f;
    for (int d = threadIdx.x; d < DD; d += 256) { float t = xr[rr][d] - mu; q += t * t; }
    q = blockReduceSum256(q);
    float rstd = rsqrtf(q * (1.f / DD) + 1e-5f);
    for (int d = threadIdx.x; d < DD; d += 256)
      xr[rr][d] = (xr[rr][d] - mu) * rstd * g[d] + b[d];
  }
  __syncthreads();
  int bidx = row0 / SS;
  int s0 = row0 % SS;
  for (int o = threadIdx.x; o < 1500; o += 256) {
    int mat = (o >= 500) + (o >= 1000);
    int rem = o - mat * 500;
    int h = rem / DHD;
    const float* Wsel = (mat == 0) ? Wq : (mat == 1) ? Wk : Wv;
    const float* bsel = (mat == 0) ? bq : (mat == 1) ? bk : bv;
    float* dst = (mat == 0) ? g_q : (mat == 1) ? g_k : g_v;
    const float* wrow = Wsel + rem * DHD;
    float w[DHD];
    #pragma unroll
    for (int d = 0; d < DHD; d++) w[d] = wrow[d];
    float bias = bsel[rem];
    size_t dbase = (((size_t)bidx * HH + h) * SS + s0) * DHD + (rem % DHD);
    #pragma unroll
    for (int rr = 0; rr < 8; rr++) {
      const float* xp = &xr[rr][h * DHD];
      float acc = bias;
      #pragma unroll
      for (int d = 0; d < DHD; d++) acc = fmaf(xp[d], w[d], acc);
      dst[dbase + (size_t)rr * DHD] = acc;
    }
  }
}

// ---------------- kernel 2: flash attention + residual --------------------------
// BM=BN=64, 256 threads (16x16), 4x4 register tiles, online softmax.
// Smem: Qt[50][66] (k-major), KP[64*66] (Kt aliased with Pt), Vs[64][64].
__global__ void __launch_bounds__(256) attn_kernel(const float* __restrict__ x) {
  __shared__ __align__(16) float Qt[DHD * 66];
  __shared__ __align__(16) float KP[64 * 66];
  __shared__ __align__(16) float Vs[64 * 64];
  int qt = blockIdx.x, bh = blockIdx.y;
  int bidx = bh / HH, h = bh - bidx * HH;
  int tid = threadIdx.x, ty = tid >> 4, tx = tid & 15;
  const float scale = 0.14142135623730951f;  // 1/sqrt(50)
  size_t base = (size_t)bh * SS * DHD;
  const float* qg = g_q + base + (size_t)qt * 64 * DHD;
  for (int idx = tid; idx < 64 * DHD; idx += 256) {
    int r = idx / DHD, d = idx - r * DHD;
    Qt[d * 66 + r] = qg[idx] * scale;
  }
  float m[4], l[4], o[4][4];
  #pragma unroll
  for (int i = 0; i < 4; i++) {
    m[i] = -1e30f; l[i] = 0.f;
    #pragma unroll
    for (int j = 0; j < 4; j++) o[i][j] = 0.f;
  }
  for (int kt = 0; kt < SS / 64; kt++) {
    __syncthreads();  // previous PV reads done (also covers Q-load on first iter)
    const float* kg = g_k + base + (size_t)kt * 64 * DHD;
    const float* vg = g_v + base + (size_t)kt * 64 * DHD;
    for (int idx = tid; idx < 64 * DHD; idx += 256) {
      int r = idx / DHD, d = idx - r * DHD;
      KP[d * 66 + r] = kg[idx];
      Vs[r * 64 + d] = vg[idx];
    }
    for (int idx = tid; idx < 64 * 16; idx += 256) {
      int r = idx >> 4, c = 48 + (idx & 15);
      if (c >= DHD) Vs[r * 64 + c] = 0.f;
    }
    __syncthreads();
    float acc[4][4];
    #pragma unroll
    for (int i = 0; i < 4; i++)
      #pragma unroll
      for (int j = 0; j < 4; j++) acc[i][j] = 0.f;
    #pragma unroll 2
    for (int d = 0; d < DHD; d++) {
      float2 q01 = *(const float2*)&Qt[d * 66 + ty * 4];
      float2 q23 = *(const float2*)&Qt[d * 66 + ty * 4 + 2];
      float2 k01 = *(const float2*)&KP[d * 66 + tx * 4];
      float2 k23 = *(const float2*)&KP[d * 66 + tx * 4 + 2];
      float qv[4] = {q01.x, q01.y, q23.x, q23.y};
      float kv[4] = {k01.x, k01.y, k23.x, k23.y};
      #pragma unroll
      for (int i = 0; i < 4; i++)
        #pragma unroll
        for (int j = 0; j < 4; j++) acc[i][j] = fmaf(qv[i], kv[j], acc[i][j]);
    }
    __syncthreads();  // all Kt reads done before Pt overwrites the same smem
    float pj[4][4];
    #pragma unroll
    for (int i = 0; i < 4; i++) {
      float mx = fmaxf(fmaxf(acc[i][0], acc[i][1]), fmaxf(acc[i][2], acc[i][3]));
      #pragma unroll
      for (int off = 8; off; off >>= 1) mx = fmaxf(mx, __shfl_xor_sync(0xffffffffu, mx, off));
      float mnew = fmaxf(m[i], mx);
      float al = __expf(m[i] - mnew);
      float rs = 0.f;
      #pragma unroll
      for (int j = 0; j < 4; j++) { pj[i][j] = __expf(acc[i][j] - mnew); rs += pj[i][j]; }
      #pragma unroll
      for (int off = 8; off; off >>= 1) rs += __shfl_xor_sync(0xffffffffu, rs, off);
      l[i] = l[i] * al + rs;
      m[i] = mnew;
      #pragma unroll
      for (int j = 0; j < 4; j++) o[i][j] *= al;
    }
    #pragma unroll
    for (int j = 0; j < 4; j++) {
      int c = tx * 4 + j;
      *(float2*)&KP[c * 66 + ty * 4]     = make_float2(pj[0][j], pj[1][j]);
      *(float2*)&KP[c * 66 + ty * 4 + 2] = make_float2(pj[2][j], pj[3][j]);
    }
    __syncthreads();
    #pragma unroll 2
    for (int kk = 0; kk < 64; kk++) {
      float2 p01 = *(const float2*)&KP[kk * 66 + ty * 4];
      float2 p23 = *(const float2*)&KP[kk * 66 + ty * 4 + 2];
      float2 v01 = *(const float2*)&Vs[kk * 64 + tx * 4];
      float2 v23 = *(const float2*)&Vs[kk * 64 + tx * 4 + 2];
      float pv[4] = {p01.x, p01.y, p23.x, p23.y};
      float vv[4] = {v01.x, v01.y, v23.x, v23.y};
      #pragma unroll
      for (int i = 0; i < 4; i++)
        #pragma unroll
        for (int j = 0; j < 4; j++) o[i][j] = fmaf(pv[i], vv[j], o[i][j]);
    }
  }
  #pragma unroll
  for (int i = 0; i < 4; i++) {
    float inv = 1.f / l[i];
    int srow = qt * 64 + ty * 4 + i;
    size_t gb = ((size_t)bidx * SS + srow) * DD + h * DHD;
    #pragma unroll
    for (int j = 0; j < 4; j++) {
      int e = tx * 4 + j;
      if (e < DHD) g_out1[gb + e] = x[gb + e] + o[i][j] * inv;
    }
  }
}

// ---------------- kernel 3: LN2 -------------------------------------------------
__global__ void __launch_bounds__(256) ln2_kernel(const float* __restrict__ g,
                                                  const float* __restrict__ b) {
  __shared__ float xr[DD];
  size_t row = blockIdx.x;
  const float* xp = g_out1 + row * DD;
  float s = 0.f;
  for (int d = threadIdx.x; d < DD; d += 256) { float v = xp[d]; xr[d] = v; s += v; }
  s = blockReduceSum256(s);
  float mu = s * (1.f / DD);
  float q = 0.f;
  for (int d = threadIdx.x; d < DD; d += 256) { float t = xr[d] - mu; q += t * t; }
  q = blockReduceSum256(q);
  float rstd = rsqrtf(q * (1.f / DD) + 1e-5f);
  float* op = g_h + row * DD;
  for (int d = threadIdx.x; d < DD; d += 256) op[d] = (xr[d] - mu) * rstd * g[d] + b[d];
}

// ---------------- kernel 4: GEMM  C = A @ W^T + bias ----------------------------
// A: [8192,500] (layer 0: g_h, layer 1: g_out2), W row-major [500,500]; C = g_t.
__global__ void __launch_bounds__(256) gemm_nt_kernel(
    const float* __restrict__ W, const float* __restrict__ bias, int layer) {
  __shared__ __align__(16) float At[32 * 66];
  __shared__ __align__(16) float Bt[32 * 66];
  const float* A = layer ? g_out2 : g_h;
  int m0 = blockIdx.x * 64, n0 = blockIdx.y * 64;
  int tid = threadIdx.x, ty = tid >> 4, tx = tid & 15;
  float acc[4][4];
  #pragma unroll
  for (int i = 0; i < 4; i++)
    #pragma unroll
    for (int j = 0; j < 4; j++) acc[i][j] = 0.f;
  for (int t = 0; t < 16; t++) {  // ceil(500/32)
    int k0 = t * 32;
    __syncthreads();
    for (int idx = tid; idx < 64 * 32; idx += 256) {
      int r = idx >> 5, kk = idx & 31;
      int k = k0 + kk;
      At[kk * 66 + r] = (k < DD) ? A[(size_t)(m0 + r) * DD + k] : 0.f;
      int c = n0 + r;
      Bt[kk * 66 + r] = (k < DD && c < DD) ? W[(size_t)c * DD + k] : 0.f;
    }
    __syncthreads();
    #pragma unroll 4
    for (int kk = 0; kk < 32; kk++) {
      float2 a01 = *(const float2*)&At[kk * 66 + ty * 4];
      float2 a23 = *(const float2*)&At[kk * 66 + ty * 4 + 2];
      float2 b01 = *(const float2*)&Bt[kk * 66 + tx * 4];
      float2 b23 = *(const float2*)&Bt[kk * 66 + tx * 4 + 2];
      float av[4] = {a01.x, a01.y, a23.x, a23.y};
      float bw[4] = {b01.x, b01.y, b23.x, b23.y};
      #pragma unroll
      for (int i = 0; i < 4; i++)
        #pragma unroll
        for (int j = 0; j < 4; j++) acc[i][j] = fmaf(av[i], bw[j], acc[i][j]);
    }
  }
  #pragma unroll
  for (int i = 0; i < 4; i++) {
    int r = m0 + ty * 4 + i;
    #pragma unroll
    for (int j = 0; j < 4; j++) {
      int c = n0 + tx * 4 + j;
      if (c < DD) g_t[(size_t)r * DD + c] = acc[i][j] + bias[c];
    }
  }
}

// ---------------- kernels 5/6: BN column stats (deterministic 2-stage) ----------
__global__ void __launch_bounds__(256) colstat_part_kernel() {
  int p = blockIdx.x;  // 128 blocks x 64 rows
  const float* base = g_t + (size_t)p * 64 * DD;
  int c = threadIdx.x;
  float s0 = 0.f, q0 = 0.f, s1 = 0.f, q1 = 0.f;
  for (int r = 0; r < 64; r++) {
    float v0 = base[r * DD + c]; s0 += v0; q0 += v0 * v0;
    if (c + 256 < DD) { float v1 = base[r * DD + c + 256]; s1 += v1; q1 += v1 * v1; }
  }
  g_part[p * DD + c] = s0; g_partq[p * DD + c] = q0;
  if (c + 256 < DD) { g_part[p * DD + c + 256] = s1; g_partq[p * DD + c + 256] = q1; }
}

__global__ void colstat_final_kernel() {
  int c = blockIdx.x * 256 + threadIdx.x;
  if (c >= DD) return;
  float s = 0.f, q = 0.f;
  for (int i = 0; i < 128; i++) { s += g_part[i * DD + c]; q += g_partq[i * DD + c]; }
  float mu = s * (1.f / NROWS);
  float var = q * (1.f / NROWS) - mu * mu;
  g_mu[c] = mu;
  g_rs[c] = rsqrtf(var + 1e-5f);
}

// ---------------- kernel 7: BN apply + ReLU + residual --------------------------
__global__ void __launch_bounds__(256) bn_apply_kernel(
    const float* __restrict__ g, const float* __restrict__ b, int layer,
    float* __restrict__ out_ext) {
  int idx = blockIdx.x * 256 + threadIdx.x;
  if (idx >= NELEM) return;
  const float* res = layer ? g_out2 : g_out1;
  float* outp = layer ? out_ext : g_out2;
  int c = idx % DD;
  float v = (g_t[idx] - g_mu[c]) * g_rs[c] * g[c] + b[c];
  outp[idx] = res[idx] + fmaxf(v, 0.f);
}

// ---------------- launch --------------------------------------------------------
extern "C" void kernel_launch(void* const* d_in, const int* in_sizes, int n_in,
                              void* d_out, int out_size) {
  (void)in_sizes; (void)n_in; (void)out_size;
  const float* x    = (const float*)d_in[0];
  const float* ln1g = (const float*)d_in[1];
  const float* ln1b = (const float*)d_in[2];
  const float* Wq   = (const float*)d_in[3];
  const float* bq   = (const float*)d_in[4];
  const float* Wk   = (const float*)d_in[5];
  const float* bk   = (const float*)d_in[6];
  const float* Wv   = (const float*)d_in[7];
  const float* bv   = (const float*)d_in[8];
  const float* ln2g = (const float*)d_in[9];
  const float* ln2b = (const float*)d_in[10];
  const float* W1   = (const float*)d_in[11];
  const float* b1   = (const float*)d_in[12];
  const float* bn1g = (const float*)d_in[13];
  const float* bn1b = (const float*)d_in[14];
  const float* W2   = (const float*)d_in[15];
  const float* b2   = (const float*)d_in[16];
  const float* bn2g = (const float*)d_in[17];
  const float* bn2b = (const float*)d_in[18];
  float* out = (float*)d_out;

  ln1_qkv_kernel<<<NROWS / 8, 256>>>(x, ln1g, ln1b, Wq, bq, Wk, bk, Wv, bv);
  attn_kernel<<<dim3(SS / 64, BB * HH), 256>>>(x);
  ln2_kernel<<<NROWS, 256>>>(ln2g, ln2b);
  gemm_nt_kernel<<<dim3(NROWS / 64, 8), 256>>>(W1, b1, 0);
  colstat_part_kernel<<<128, 256>>>();
  colstat_final_kernel<<<2, 256>>>();
  bn_apply_kernel<<<(NELEM + 255) / 256, 256>>>(bn1g, bn1b, 0, out);
  gemm_nt_kernel<<<dim3(NROWS / 64, 8), 256>>>(W2, b2, 1);
  colstat_part_kernel<<<128, 256>>>();
  colstat_final_kernel<<<2, 256>>>();
  bn_apply_kernel<<<(NELEM + 255) / 256, 256>>>(bn2g, bn2b, 1, out);
}

// round 3
// speedup vs baseline: 1.0879x; 1.0872x over previous
#include <cuda_runtime.h>

typedef unsigned long long ull;

#define BB 4
#define SS 2048
#define DD 500
#define HH 10
#define DHD 50
#define NROWS 8192
#define NELEM 4096000

// ---------------- scratch ------------------------------------------------------
__device__ float g_q[NELEM];
__device__ float g_k[NELEM];
__device__ float g_v[NELEM];
__device__ float g_out1[NELEM];
__device__ float g_h[NELEM];
__device__ float g_t[NELEM];
__device__ float g_out2[NELEM];
__device__ float g_part[128 * DD];
__device__ float g_partq[128 * DD];
__device__ float g_mu[DD];
__device__ float g_rs[DD];

// ---------------- f32x2 helpers -------------------------------------------------
__device__ __forceinline__ void ffma2(ull& d, ull a, ull b) {
  asm("fma.rn.f32x2 %0, %1, %2, %0;" : "+l"(d) : "l"(a), "l"(b));
}
__device__ __forceinline__ ull mul2(ull a, ull b) {
  ull r; asm("mul.rn.f32x2 %0, %1, %2;" : "=l"(r) : "l"(a), "l"(b)); return r;
}
__device__ __forceinline__ ull dup2(float x) {
  ull r; asm("mov.b64 %0, {%1, %1};" : "=l"(r) : "f"(x)); return r;
}
__device__ __forceinline__ ull pack2(float lo, float hi) {
  ull r; asm("mov.b64 %0, {%1, %2};" : "=l"(r) : "f"(lo), "f"(hi)); return r;
}
__device__ __forceinline__ float2 unpack2(ull v) {
  float2 r; asm("mov.b64 {%0, %1}, %2;" : "=f"(r.x), "=f"(r.y) : "l"(v)); return r;
}

__device__ __forceinline__ float blockReduceSum256(float v) {
  __shared__ float sh[8];
  #pragma unroll
  for (int off = 16; off; off >>= 1) v += __shfl_xor_sync(0xffffffffu, v, off);
  if ((threadIdx.x & 31) == 0) sh[threadIdx.x >> 5] = v;
  __syncthreads();
  if (threadIdx.x < 32) {
    float t = (threadIdx.x < 8) ? sh[threadIdx.x] : 0.f;
    #pragma unroll
    for (int off = 4; off; off >>= 1) t += __shfl_xor_sync(0xffffffffu, t, off);
    if (threadIdx.x == 0) sh[0] = t;
  }
  __syncthreads();
  float r = sh[0];
  __syncthreads();
  return r;
}

// ---------------- kernel 1: LN1 + QKV projection (unchanged) --------------------
__global__ void __launch_bounds__(256) ln1_qkv_kernel(
    const float* __restrict__ x,
    const float* __restrict__ g, const float* __restrict__ b,
    const float* __restrict__ Wq, const float* __restrict__ bq,
    const float* __restrict__ Wk, const float* __restrict__ bk,
    const float* __restrict__ Wv, const float* __restrict__ bv) {
  __shared__ float xr[8][DD];
  int row0 = blockIdx.x * 8;
  for (int rr = 0; rr < 8; rr++) {
    const float* xp = x + (size_t)(row0 + rr) * DD;
    float s = 0.f;
    for (int d = threadIdx.x; d < DD; d += 256) { float v = xp[d]; xr[rr][d] = v; s += v; }
    s = blockReduceSum256(s);
    float mu = s * (1.f / DD);
    float q = 0.f;
    for (int d = threadIdx.x; d < DD; d += 256) { float t = xr[rr][d] - mu; q += t * t; }
    q = blockReduceSum256(q);
    float rstd = rsqrtf(q * (1.f / DD) + 1e-5f);
    for (int d = threadIdx.x; d < DD; d += 256)
      xr[rr][d] = (xr[rr][d] - mu) * rstd * g[d] + b[d];
  }
  __syncthreads();
  int bidx = row0 / SS;
  int s0 = row0 % SS;
  for (int o = threadIdx.x; o < 1500; o += 256) {
    int mat = (o >= 500) + (o >= 1000);
    int rem = o - mat * 500;
    int h = rem / DHD;
    const float* Wsel = (mat == 0) ? Wq : (mat == 1) ? Wk : Wv;
    const float* bsel = (mat == 0) ? bq : (mat == 1) ? bk : bv;
    float* dst = (mat == 0) ? g_q : (mat == 1) ? g_k : g_v;
    const float* wrow = Wsel + rem * DHD;
    float w[DHD];
    #pragma unroll
    for (int d = 0; d < DHD; d++) w[d] = wrow[d];
    float bias = bsel[rem];
    size_t dbase = (((size_t)bidx * HH + h) * SS + s0) * DHD + (rem % DHD);
    #pragma unroll
    for (int rr = 0; rr < 8; rr++) {
      const float* xp = &xr[rr][h * DHD];
      float acc = bias;
      #pragma unroll
      for (int d = 0; d < DHD; d++) acc = fmaf(xp[d], w[d], acc);
      dst[dbase + (size_t)rr * DHD] = acc;
    }
  }
}

// ---------------- kernel 2: flash attention, 128x64, f32x2, 8x4 tiles -----------
// dyn smem layout (floats): Qt[50*132] | KP[8192] (K as [d*68+c], P swizzled) |
// Vs[64*68]. Total 19144 floats = 76576 B.
#define QT_OFF 0
#define KP_OFF 6600
#define VS_OFF 14792
#define ATT_SMEM 76576

__global__ void __launch_bounds__(256, 2) attn_kernel(const float* __restrict__ x) {
  extern __shared__ float sm[];
  float* Qt = sm + QT_OFF;
  float* KP = sm + KP_OFF;
  float* Vs = sm + VS_OFF;
  int qt = blockIdx.x, bh = blockIdx.y;
  int bidx = bh / HH, h = bh - bidx * HH;
  int tid = threadIdx.x, ty = tid >> 4, tx = tid & 15;
  const float scale = 0.14142135623730951f;  // 1/sqrt(50)
  size_t base = (size_t)bh * SS * DHD;
  const float* qg = g_q + base + (size_t)qt * 128 * DHD;
  // Q staged transposed+scaled: Qt[d*132 + r]
  for (int idx = tid; idx < 128 * DHD; idx += 256) {
    int r = idx / DHD, d = idx - r * DHD;
    Qt[d * 132 + r] = qg[idx] * scale;
  }
  // zero V pad cols [50,68)
  for (int idx = tid; idx < 64 * 18; idx += 256) {
    int r = idx / 18, c = DHD + idx % 18;
    Vs[r * 68 + c] = 0.f;
  }
  float m[8], l[8];
  ull o2[4][4];
  #pragma unroll
  for (int i = 0; i < 8; i++) { m[i] = -1e30f; l[i] = 0.f; }
  #pragma unroll
  for (int i = 0; i < 4; i++)
    #pragma unroll
    for (int j = 0; j < 4; j++) o2[i][j] = 0ull;

  for (int kt = 0; kt < SS / 64; kt++) {
    __syncthreads();  // prev PV reads done
    const float* kg = g_k + base + (size_t)kt * 64 * DHD;
    const float* vg = g_v + base + (size_t)kt * 64 * DHD;
    // stage K transposed (KP[d*68+c]) and V row-major via float2 loads
    for (int idx = tid; idx < 64 * 25; idx += 256) {
      int c = idx / 25, d2 = idx - c * 25;
      float2 kf = ((const float2*)kg)[idx];
      KP[(2 * d2) * 68 + c] = kf.x;
      KP[(2 * d2 + 1) * 68 + c] = kf.y;
      float2 vf = ((const float2*)vg)[idx];
      *(float2*)&Vs[c * 68 + 2 * d2] = vf;
    }
    __syncthreads();
    // ---- S = Q K^T ----
    ull acc2[4][4];
    #pragma unroll
    for (int i = 0; i < 4; i++)
      #pragma unroll
      for (int j = 0; j < 4; j++) acc2[i][j] = 0ull;
    #pragma unroll 2
    for (int d = 0; d < DHD; d++) {
      float4 qa = *(const float4*)&Qt[d * 132 + ty * 8];
      float4 qb = *(const float4*)&Qt[d * 132 + ty * 8 + 4];
      float4 k4 = *(const float4*)&KP[d * 68 + tx * 4];
      ull q2[4] = {pack2(qa.x, qa.y), pack2(qa.z, qa.w),
                   pack2(qb.x, qb.y), pack2(qb.z, qb.w)};
      ull kd[4] = {dup2(k4.x), dup2(k4.y), dup2(k4.z), dup2(k4.w)};
      #pragma unroll
      for (int i = 0; i < 4; i++)
        #pragma unroll
        for (int j = 0; j < 4; j++) ffma2(acc2[i][j], q2[i], kd[j]);
    }
    __syncthreads();  // K reads done before P overwrite
    // ---- online softmax ----
    float a[8][4], al[8];
    #pragma unroll
    for (int i2 = 0; i2 < 4; i2++)
      #pragma unroll
      for (int j = 0; j < 4; j++) {
        float2 t = unpack2(acc2[i2][j]);
        a[2 * i2][j] = t.x; a[2 * i2 + 1][j] = t.y;
      }
    #pragma unroll
    for (int i = 0; i < 8; i++) {
      float mx = fmaxf(fmaxf(a[i][0], a[i][1]), fmaxf(a[i][2], a[i][3]));
      #pragma unroll
      for (int off = 8; off; off >>= 1) mx = fmaxf(mx, __shfl_xor_sync(0xffffffffu, mx, off));
      float mnew = fmaxf(m[i], mx);
      al[i] = __expf(m[i] - mnew);
      float rs = 0.f;
      #pragma unroll
      for (int j = 0; j < 4; j++) { a[i][j] = __expf(a[i][j] - mnew); rs += a[i][j]; }
      #pragma unroll
      for (int off = 8; off; off >>= 1) rs += __shfl_xor_sync(0xffffffffu, rs, off);
      l[i] = l[i] * al[i] + rs;
      m[i] = mnew;
    }
    #pragma unroll
    for (int i2 = 0; i2 < 4; i2++) {
      ull alp = pack2(al[2 * i2], al[2 * i2 + 1]);
      #pragma unroll
      for (int j = 0; j < 4; j++) o2[i2][j] = mul2(o2[i2][j], alp);
    }
    // ---- store P col-major, rotation swizzle: slot=(r4 + (kk>>2)) & 31 ----
    #pragma unroll
    for (int j = 0; j < 4; j++) {
      int kk = tx * 4 + j;
      int sb = kk >> 2;
      float4 lo = make_float4(a[0][j], a[1][j], a[2][j], a[3][j]);
      float4 hi = make_float4(a[4][j], a[5][j], a[6][j], a[7][j]);
      *(float4*)&KP[kk * 128 + (((ty * 2) + sb) & 31) * 4] = lo;
      *(float4*)&KP[kk * 128 + (((ty * 2 + 1) + sb) & 31) * 4] = hi;
    }
    __syncthreads();
    // ---- O += P V ----
    #pragma unroll 2
    for (int kk = 0; kk < 64; kk++) {
      int sb = kk >> 2;
      float4 pa = *(const float4*)&KP[kk * 128 + (((ty * 2) + sb) & 31) * 4];
      float4 pb = *(const float4*)&KP[kk * 128 + (((ty * 2 + 1) + sb) & 31) * 4];
      float4 v4 = *(const float4*)&Vs[kk * 68 + tx * 4];
      ull p2[4] = {pack2(pa.x, pa.y), pack2(pa.z, pa.w),
                   pack2(pb.x, pb.y), pack2(pb.z, pb.w)};
      ull vd[4] = {dup2(v4.x), dup2(v4.y), dup2(v4.z), dup2(v4.w)};
      #pragma unroll
      for (int i = 0; i < 4; i++)
        #pragma unroll
        for (int j = 0; j < 4; j++) ffma2(o2[i][j], p2[i], vd[j]);
    }
  }
  // ---- epilogue: normalize + residual ----
  float ov[8][4];
  #pragma unroll
  for (int i2 = 0; i2 < 4; i2++)
    #pragma unroll
    for (int j = 0; j < 4; j++) {
      float2 t = unpack2(o2[i2][j]);
      ov[2 * i2][j] = t.x; ov[2 * i2 + 1][j] = t.y;
    }
  #pragma unroll
  for (int i = 0; i < 8; i++) {
    float inv = 1.f / l[i];
    int srow = qt * 128 + ty * 8 + i;
    size_t gb = ((size_t)bidx * SS + srow) * DD + h * DHD;
    #pragma unroll
    for (int j = 0; j < 4; j++) {
      int e = tx * 4 + j;
      if (e < DHD) g_out1[gb + e] = x[gb + e] + ov[i][j] * inv;
    }
  }
}

// ---------------- kernel 3: LN2 (unchanged) -------------------------------------
__global__ void __launch_bounds__(256) ln2_kernel(const float* __restrict__ g,
                                                  const float* __restrict__ b) {
  __shared__ float xr[DD];
  size_t row = blockIdx.x;
  const float* xp = g_out1 + row * DD;
  float s = 0.f;
  for (int d = threadIdx.x; d < DD; d += 256) { float v = xp[d]; xr[d] = v; s += v; }
  s = blockReduceSum256(s);
  float mu = s * (1.f / DD);
  float q = 0.f;
  for (int d = threadIdx.x; d < DD; d += 256) { float t = xr[d] - mu; q += t * t; }
  q = blockReduceSum256(q);
  float rstd = rsqrtf(q * (1.f / DD) + 1e-5f);
  float* op = g_h + row * DD;
  for (int d = threadIdx.x; d < DD; d += 256) op[d] = (xr[d] - mu) * rstd * g[d] + b[d];
}

// ---------------- kernel 4: GEMM C = A @ W^T + bias, 128x64, f32x2 --------------
__global__ void __launch_bounds__(256) gemm_nt_kernel(
    const float* __restrict__ W, const float* __restrict__ bias, int layer) {
  __shared__ __align__(16) float At[32 * 132];
  __shared__ __align__(16) float Wt[32 * 68];
  const float* A = layer ? g_out2 : g_h;
  int m0 = blockIdx.x * 128, n0 = blockIdx.y * 64;
  int tid = threadIdx.x, ty = tid >> 4, tx = tid & 15;
  ull acc2[4][4];
  #pragma unroll
  for (int i = 0; i < 4; i++)
    #pragma unroll
    for (int j = 0; j < 4; j++) acc2[i][j] = 0ull;
  for (int t = 0; t < 16; t++) {
    int k0 = t * 32;
    __syncthreads();
    for (int idx = tid; idx < 128 * 32; idx += 256) {
      int r = idx >> 5, kk = idx & 31;
      int k = k0 + kk;
      At[kk * 132 + r] = (k < DD) ? A[(size_t)(m0 + r) * DD + k] : 0.f;
    }
    for (int idx = tid; idx < 64 * 32; idx += 256) {
      int r = idx >> 5, kk = idx & 31;
      int k = k0 + kk, c = n0 + r;
      Wt[kk * 68 + r] = (k < DD && c < DD) ? W[(size_t)c * DD + k] : 0.f;
    }
    __syncthreads();
    #pragma unroll 4
    for (int kk = 0; kk < 32; kk++) {
      float4 aa = *(const float4*)&At[kk * 132 + ty * 8];
      float4 ab = *(const float4*)&At[kk * 132 + ty * 8 + 4];
      float4 w4 = *(const float4*)&Wt[kk * 68 + tx * 4];
      ull a2[4] = {pack2(aa.x, aa.y), pack2(aa.z, aa.w),
                   pack2(ab.x, ab.y), pack2(ab.z, ab.w)};
      ull wd[4] = {dup2(w4.x), dup2(w4.y), dup2(w4.z), dup2(w4.w)};
      #pragma unroll
      for (int i = 0; i < 4; i++)
        #pragma unroll
        for (int j = 0; j < 4; j++) ffma2(acc2[i][j], a2[i], wd[j]);
    }
  }
  #pragma unroll
  for (int i2 = 0; i2 < 4; i2++)
    #pragma unroll
    for (int j = 0; j < 4; j++) {
      float2 v = unpack2(acc2[i2][j]);
      int c = n0 + tx * 4 + j;
      if (c < DD) {
        int r = m0 + ty * 8 + 2 * i2;
        float bs = bias[c];
        g_t[(size_t)r * DD + c] = v.x + bs;
        g_t[(size_t)(r + 1) * DD + c] = v.y + bs;
      }
    }
}

// ---------------- kernels 5/6: BN column stats (unchanged) ----------------------
__global__ void __launch_bounds__(256) colstat_part_kernel() {
  int p = blockIdx.x;
  const float* base = g_t + (size_t)p * 64 * DD;
  int c = threadIdx.x;
  float s0 = 0.f, q0 = 0.f, s1 = 0.f, q1 = 0.f;
  for (int r = 0; r < 64; r++) {
    float v0 = base[r * DD + c]; s0 += v0; q0 += v0 * v0;
    if (c + 256 < DD) { float v1 = base[r * DD + c + 256]; s1 += v1; q1 += v1 * v1; }
  }
  g_part[p * DD + c] = s0; g_partq[p * DD + c] = q0;
  if (c + 256 < DD) { g_part[p * DD + c + 256] = s1; g_partq[p * DD + c + 256] = q1; }
}

__global__ void colstat_final_kernel() {
  int c = blockIdx.x * 256 + threadIdx.x;
  if (c >= DD) return;
  float s = 0.f, q = 0.f;
  for (int i = 0; i < 128; i++) { s += g_part[i * DD + c]; q += g_partq[i * DD + c]; }
  float mu = s * (1.f / NROWS);
  float var = q * (1.f / NROWS) - mu * mu;
  g_mu[c] = mu;
  g_rs[c] = rsqrtf(var + 1e-5f);
}

// ---------------- kernel 7: BN apply + ReLU + residual (unchanged) --------------
__global__ void __launch_bounds__(256) bn_apply_kernel(
    const float* __restrict__ g, const float* __restrict__ b, int layer,
    float* __restrict__ out_ext) {
  int idx = blockIdx.x * 256 + threadIdx.x;
  if (idx >= NELEM) return;
  const float* res = layer ? g_out2 : g_out1;
  float* outp = layer ? out_ext : g_out2;
  int c = idx % DD;
  float v = (g_t[idx] - g_mu[c]) * g_rs[c] * g[c] + b[c];
  outp[idx] = res[idx] + fmaxf(v, 0.f);
}

// ---------------- launch --------------------------------------------------------
extern "C" void kernel_launch(void* const* d_in, const int* in_sizes, int n_in,
                              void* d_out, int out_size) {
  (void)in_sizes; (void)n_in; (void)out_size;
  const float* x    = (const float*)d_in[0];
  const float* ln1g = (const float*)d_in[1];
  const float* ln1b = (const float*)d_in[2];
  const float* Wq   = (const float*)d_in[3];
  const float* bq   = (const float*)d_in[4];
  const float* Wk   = (const float*)d_in[5];
  const float* bk   = (const float*)d_in[6];
  const float* Wv   = (const float*)d_in[7];
  const float* bv   = (const float*)d_in[8];
  const float* ln2g = (const float*)d_in[9];
  const float* ln2b = (const float*)d_in[10];
  const float* W1   = (const float*)d_in[11];
  const float* b1   = (const float*)d_in[12];
  const float* bn1g = (const float*)d_in[13];
  const float* bn1b = (const float*)d_in[14];
  const float* W2   = (const float*)d_in[15];
  const float* b2   = (const float*)d_in[16];
  const float* bn2g = (const float*)d_in[17];
  const float* bn2b = (const float*)d_in[18];
  float* out = (float*)d_out;

  cudaFuncSetAttribute(attn_kernel, cudaFuncAttributeMaxDynamicSharedMemorySize, ATT_SMEM);

  ln1_qkv_kernel<<<NROWS / 8, 256>>>(x, ln1g, ln1b, Wq, bq, Wk, bk, Wv, bv);
  attn_kernel<<<dim3(SS / 128, BB * HH), 256, ATT_SMEM>>>(x);
  ln2_kernel<<<NROWS, 256>>>(ln2g, ln2b);
  gemm_nt_kernel<<<dim3(NROWS / 128, 8), 256>>>(W1, b1, 0);
  colstat_part_kernel<<<128, 256>>>();
  colstat_final_kernel<<<2, 256>>>();
  bn_apply_kernel<<<(NELEM + 255) / 256, 256>>>(bn1g, bn1b, 0, out);
  gemm_nt_kernel<<<dim3(NROWS / 128, 8), 256>>>(W2, b2, 1);
  colstat_part_kernel<<<128, 256>>>();
  colstat_final_kernel<<<2, 256>>>();
  bn_apply_kernel<<<(NELEM + 255) / 256, 256>>>(bn2g, bn2b, 1, out);
}

// round 6
// speedup vs baseline: 2.2400x; 2.0589x over previous
#include <cuda_runtime.h>
#include <cstdint>

#define BB 4
#define SS 2048
#define DD 500
#define HH 10
#define DHD 50
#define NROWS 8192
#define NELEM 4096000
#define QKV_LD 64
#define NQKV (BB * HH * SS * QKV_LD)

// ---------------- scratch ------------------------------------------------------
__device__ float g_q[NQKV];
__device__ float g_k[NQKV];
__device__ float g_v[NQKV];
__device__ float g_out1[NELEM];
__device__ float g_h[NELEM];
__device__ float g_t[NELEM];
__device__ float g_out2[NELEM];
__device__ float g_part[128 * DD];
__device__ float g_partq[128 * DD];
__device__ float g_mu[DD];
__device__ float g_rs[DD];

// ---------------- helpers ------------------------------------------------------
__device__ __forceinline__ float to_tf32(float x) {
  uint32_t r;
  asm("cvt.rna.tf32.f32 %0, %1;" : "=r"(r) : "f"(x));
  return __uint_as_float(r);
}
// D += A(16x8) * B(8x8), tf32
__device__ __forceinline__ void mma8(float* c, const uint32_t* a, const uint32_t* b) {
  asm volatile(
      "mma.sync.aligned.m16n8k8.row.col.f32.tf32.tf32.f32 "
      "{%0,%1,%2,%3},{%4,%5,%6,%7},{%8,%9},{%0,%1,%2,%3};"
      : "+f"(c[0]), "+f"(c[1]), "+f"(c[2]), "+f"(c[3])
      : "r"(a[0]), "r"(a[1]), "r"(a[2]), "r"(a[3]), "r"(b[0]), "r"(b[1]));
}
__device__ __forceinline__ uint32_t ldsu(const float* p) {
  return __float_as_uint(*p);
}

__device__ __forceinline__ float blockReduceSum256(float v) {
  __shared__ float sh[8];
  #pragma unroll
  for (int off = 16; off; off >>= 1) v += __shfl_xor_sync(0xffffffffu, v, off);
  if ((threadIdx.x & 31) == 0) sh[threadIdx.x >> 5] = v;
  __syncthreads();
  if (threadIdx.x < 32) {
    float t = (threadIdx.x < 8) ? sh[threadIdx.x] : 0.f;
    #pragma unroll
    for (int off = 4; off; off >>= 1) t += __shfl_xor_sync(0xffffffffu, t, off);
    if (threadIdx.x == 0) sh[0] = t;
  }
  __syncthreads();
  float r = sh[0];
  __syncthreads();
  return r;
}

// ---------------- kernel 1: LN1 + QKV projection (stride-64 padded out) ---------
__global__ void __launch_bounds__(256) ln1_qkv_kernel(
    const float* __restrict__ x,
    const float* __restrict__ g, const float* __restrict__ b,
    const float* __restrict__ Wq, const float* __restrict__ bq,
    const float* __restrict__ Wk, const float* __restrict__ bk,
    const float* __restrict__ Wv, const float* __restrict__ bv) {
  __shared__ float xr[8][DD];
  int row0 = blockIdx.x * 8;
  for (int rr = 0; rr < 8; rr++) {
    const float* xp = x + (size_t)(row0 + rr) * DD;
    float s = 0.f;
    for (int d = threadIdx.x; d < DD; d += 256) { float v = xp[d]; xr[rr][d] = v; s += v; }
    s = blockReduceSum256(s);
    float mu = s * (1.f / DD);
    float q = 0.f;
    for (int d = threadIdx.x; d < DD; d += 256) { float t = xr[rr][d] - mu; q += t * t; }
    q = blockReduceSum256(q);
    float rstd = rsqrtf(q * (1.f / DD) + 1e-5f);
    for (int d = threadIdx.x; d < DD; d += 256)
      xr[rr][d] = (xr[rr][d] - mu) * rstd * g[d] + b[d];
  }
  __syncthreads();
  int bidx = row0 / SS;
  int s0 = row0 % SS;
  for (int o = threadIdx.x; o < 1920; o += 256) {
    int mat = o / 640;
    int rem = o - mat * 640;
    int h = rem / QKV_LD;
    int e = rem - h * QKV_LD;
    float* dst = (mat == 0) ? g_q : (mat == 1) ? g_k : g_v;
    size_t dbase = (((size_t)bidx * HH + h) * SS + s0) * QKV_LD + e;
    if (e < DHD) {
      const float* Wsel = (mat == 0) ? Wq : (mat == 1) ? Wk : Wv;
      const float* bsel = (mat == 0) ? bq : (mat == 1) ? bk : bv;
      const float* wrow = Wsel + (h * DHD + e) * DHD;
      float w[DHD];
      #pragma unroll
      for (int d = 0; d < DHD; d++) w[d] = wrow[d];
      float bias = bsel[h * DHD + e];
      #pragma unroll
      for (int rr = 0; rr < 8; rr++) {
        const float* xp = &xr[rr][h * DHD];
        float acc = bias;
        #pragma unroll
        for (int d = 0; d < DHD; d++) acc = fmaf(xp[d], w[d], acc);
        dst[dbase + (size_t)rr * QKV_LD] = acc;
      }
    } else {
      #pragma unroll
      for (int rr = 0; rr < 8; rr++) dst[dbase + (size_t)rr * QKV_LD] = 0.f;
    }
  }
}

// ---------------- kernel 2: mma.sync tf32 flash attention -----------------------
// smem floats: Q[128][68] @0 | K[64][68] @8704 | V[64][72] @13056 | P[128][68] @17664
#define ATT_SMEM 105472

__global__ void __launch_bounds__(128, 2) attn_mma_kernel(const float* __restrict__ x) {
  extern __shared__ float sm[];
  float* Qs = sm;
  float* Ks = sm + 8704;
  float* Vs = sm + 13056;
  float* Ps = sm + 17664;
  int tid = threadIdx.x, w = tid >> 5, lane = tid & 31;
  int g = lane >> 2, tig = lane & 3;
  int qt = blockIdx.x, bh = blockIdx.y;
  int bidx = bh / HH, h = bh - bidx * HH;
  const float scale = 0.14142135623730951f;

  // stage Q (scaled, tf32)
  const float4* qg4 = (const float4*)(g_q + ((size_t)bh * SS + (size_t)qt * 128) * QKV_LD);
  for (int i = tid; i < 2048; i += 128) {
    int r = i >> 4, c4 = i & 15;
    float4 v = qg4[i];
    v.x = to_tf32(v.x * scale); v.y = to_tf32(v.y * scale);
    v.z = to_tf32(v.z * scale); v.w = to_tf32(v.w * scale);
    *(float4*)&Qs[r * 68 + c4 * 4] = v;
  }

  float S[2][8][4], O[2][8][4], mrow[2][2], lrow[2][2];
  #pragma unroll
  for (int mt = 0; mt < 2; mt++) {
    mrow[mt][0] = -1e30f; mrow[mt][1] = -1e30f;
    lrow[mt][0] = 0.f; lrow[mt][1] = 0.f;
    #pragma unroll
    for (int n = 0; n < 8; n++)
      #pragma unroll
      for (int c = 0; c < 4; c++) O[mt][n][c] = 0.f;
  }

  const float4* kg4 = (const float4*)(g_k + (size_t)bh * SS * QKV_LD);
  const float4* vg4 = (const float4*)(g_v + (size_t)bh * SS * QKV_LD);
  int qrow0 = w * 32 + g;

  for (int kt = 0; kt < 32; kt++) {
    __syncthreads();
    for (int i = tid; i < 1024; i += 128) {
      int r = i >> 4, c4 = i & 15;
      float4 kv = kg4[kt * 1024 + i];
      kv.x = to_tf32(kv.x); kv.y = to_tf32(kv.y);
      kv.z = to_tf32(kv.z); kv.w = to_tf32(kv.w);
      *(float4*)&Ks[r * 68 + c4 * 4] = kv;
      float4 vv = vg4[kt * 1024 + i];
      vv.x = to_tf32(vv.x); vv.y = to_tf32(vv.y);
      vv.z = to_tf32(vv.z); vv.w = to_tf32(vv.w);
      *(float4*)&Vs[r * 72 + c4 * 4] = vv;
    }
    __syncthreads();

    // ---- S = Q K^T ----
    #pragma unroll
    for (int mt = 0; mt < 2; mt++)
      #pragma unroll
      for (int n = 0; n < 8; n++)
        #pragma unroll
        for (int c = 0; c < 4; c++) S[mt][n][c] = 0.f;
    #pragma unroll
    for (int k = 0; k < 8; k++) {
      uint32_t a[2][4];
      #pragma unroll
      for (int mt = 0; mt < 2; mt++) {
        int r = qrow0 + mt * 16;
        a[mt][0] = ldsu(&Qs[r * 68 + k * 8 + tig]);
        a[mt][1] = ldsu(&Qs[(r + 8) * 68 + k * 8 + tig]);
        a[mt][2] = ldsu(&Qs[r * 68 + k * 8 + tig + 4]);
        a[mt][3] = ldsu(&Qs[(r + 8) * 68 + k * 8 + tig + 4]);
      }
      #pragma unroll
      for (int n = 0; n < 8; n++) {
        uint32_t b[2];
        b[0] = ldsu(&Ks[(n * 8 + g) * 68 + k * 8 + tig]);
        b[1] = ldsu(&Ks[(n * 8 + g) * 68 + k * 8 + tig + 4]);
        mma8(S[0][n], a[0], b);
        mma8(S[1][n], a[1], b);
      }
    }

    // ---- online softmax (rows: g + rr*8 per m-tile) ----
    #pragma unroll
    for (int mt = 0; mt < 2; mt++) {
      #pragma unroll
      for (int rr = 0; rr < 2; rr++) {
        float mx = -1e30f;
        #pragma unroll
        for (int n = 0; n < 8; n++)
          mx = fmaxf(mx, fmaxf(S[mt][n][2 * rr], S[mt][n][2 * rr + 1]));
        mx = fmaxf(mx, __shfl_xor_sync(0xffffffffu, mx, 1));
        mx = fmaxf(mx, __shfl_xor_sync(0xffffffffu, mx, 2));
        float mold = mrow[mt][rr];
        float mnew = fmaxf(mold, mx);
        float alpha = __expf(mold - mnew);
        float rs = 0.f;
        int prow = qrow0 + mt * 16 + rr * 8;
        #pragma unroll
        for (int n = 0; n < 8; n++) {
          float p0 = __expf(S[mt][n][2 * rr] - mnew);
          float p1 = __expf(S[mt][n][2 * rr + 1] - mnew);
          rs += p0 + p1;
          *(float2*)&Ps[prow * 68 + n * 8 + 2 * tig] =
              make_float2(to_tf32(p0), to_tf32(p1));
          O[mt][n][2 * rr] *= alpha;
          O[mt][n][2 * rr + 1] *= alpha;
        }
        rs += __shfl_xor_sync(0xffffffffu, rs, 1);
        rs += __shfl_xor_sync(0xffffffffu, rs, 2);
        lrow[mt][rr] = lrow[mt][rr] * alpha + rs;
        mrow[mt][rr] = mnew;
      }
    }
    __syncwarp();

    // ---- O += P V ----
    #pragma unroll
    for (int k = 0; k < 8; k++) {
      uint32_t a[2][4];
      #pragma unroll
      for (int mt = 0; mt < 2; mt++) {
        int r = qrow0 + mt * 16;
        a[mt][0] = ldsu(&Ps[r * 68 + k * 8 + tig]);
        a[mt][1] = ldsu(&Ps[(r + 8) * 68 + k * 8 + tig]);
        a[mt][2] = ldsu(&Ps[r * 68 + k * 8 + tig + 4]);
        a[mt][3] = ldsu(&Ps[(r + 8) * 68 + k * 8 + tig + 4]);
      }
      #pragma unroll
      for (int n = 0; n < 8; n++) {
        uint32_t b[2];
        b[0] = ldsu(&Vs[(k * 8 + tig) * 72 + n * 8 + g]);
        b[1] = ldsu(&Vs[(k * 8 + tig + 4) * 72 + n * 8 + g]);
        mma8(O[0][n], a[0], b);
        mma8(O[1][n], a[1], b);
      }
    }
  }

  // ---- epilogue: normalize + residual ----
  #pragma unroll
  for (int mt = 0; mt < 2; mt++) {
    #pragma unroll
    for (int rr = 0; rr < 2; rr++) {
      float inv = 1.f / lrow[mt][rr];
      int grow = qt * 128 + qrow0 + mt * 16 + rr * 8;
      size_t gb = ((size_t)bidx * SS + grow) * DD + (size_t)h * DHD;
      #pragma unroll
      for (int n = 0; n < 7; n++) {
        int d0 = n * 8 + 2 * tig;
        if (d0 < DHD) {
          float2 xv = *(const float2*)(x + gb + d0);
          *(float2*)(g_out1 + gb + d0) =
              make_float2(xv.x + O[mt][n][2 * rr] * inv,
                          xv.y + O[mt][n][2 * rr + 1] * inv);
        }
      }
    }
  }
}

// ---------------- kernel 3: LN2 --------------------------------------------------
__global__ void __launch_bounds__(256) ln2_kernel(const float* __restrict__ g,
                                                  const float* __restrict__ b) {
  __shared__ float xr[DD];
  size_t row = blockIdx.x;
  const float* xp = g_out1 + row * DD;
  float s = 0.f;
  for (int d = threadIdx.x; d < DD; d += 256) { float v = xp[d]; xr[d] = v; s += v; }
  s = blockReduceSum256(s);
  float mu = s * (1.f / DD);
  float q = 0.f;
  for (int d = threadIdx.x; d < DD; d += 256) { float t = xr[d] - mu; q += t * t; }
  q = blockReduceSum256(q);
  float rstd = rsqrtf(q * (1.f / DD) + 1e-5f);
  float* op = g_h + row * DD;
  for (int d = threadIdx.x; d < DD; d += 256) op[d] = (xr[d] - mu) * rstd * g[d] + b[d];
}

// ---------------- kernel 4: mma.sync tf32 GEMM C = A @ W^T + bias ----------------
// CTA tile 128x64, 8 warps (4m x 2n), k-chunks of 32.
__global__ void __launch_bounds__(256) gemm_mma_kernel(
    const float* __restrict__ Wm, const float* __restrict__ bias, int layer) {
  __shared__ float As[128 * 36];
  __shared__ float Bs[64 * 36];
  const float* A = layer ? g_out2 : g_h;
  int m0 = blockIdx.x * 128, n0 = blockIdx.y * 64;
  int tid = threadIdx.x, w = tid >> 5, lane = tid & 31;
  int g = lane >> 2, tig = lane & 3;
  int wm = w >> 1, wn = w & 1;
  float C[2][4][4];
  #pragma unroll
  for (int mt = 0; mt < 2; mt++)
    #pragma unroll
    for (int nt = 0; nt < 4; nt++)
      #pragma unroll
      for (int c = 0; c < 4; c++) C[mt][nt][c] = 0.f;

  for (int ch = 0; ch < 16; ch++) {
    int k0 = ch * 32;
    __syncthreads();
    // A tile 128x32 (float2 path, tf32)
    for (int i = tid; i < 2048; i += 256) {
      int r = i >> 4, c2 = i & 15;
      int k = k0 + c2 * 2;
      float2 v = (k < DD) ? *(const float2*)(A + (size_t)(m0 + r) * DD + k)
                          : make_float2(0.f, 0.f);
      v.x = to_tf32(v.x); v.y = to_tf32(v.y);
      *(float2*)&As[r * 36 + c2 * 2] = v;
    }
    // W tile 64x32
    for (int i = tid; i < 1024; i += 256) {
      int r = i >> 4, c2 = i & 15;
      int k = k0 + c2 * 2, row = n0 + r;
      float2 v = (k < DD && row < DD)
                     ? *(const float2*)(Wm + (size_t)row * DD + k)
                     : make_float2(0.f, 0.f);
      v.x = to_tf32(v.x); v.y = to_tf32(v.y);
      *(float2*)&Bs[r * 36 + c2 * 2] = v;
    }
    __syncthreads();
    #pragma unroll
    for (int k = 0; k < 4; k++) {
      uint32_t a[2][4];
      #pragma unroll
      for (int mt = 0; mt < 2; mt++) {
        int r = wm * 32 + mt * 16 + g;
        a[mt][0] = ldsu(&As[r * 36 + k * 8 + tig]);
        a[mt][1] = ldsu(&As[(r + 8) * 36 + k * 8 + tig]);
        a[mt][2] = ldsu(&As[r * 36 + k * 8 + tig + 4]);
        a[mt][3] = ldsu(&As[(r + 8) * 36 + k * 8 + tig + 4]);
      }
      #pragma unroll
      for (int nt = 0; nt < 4; nt++) {
        uint32_t b[2];
        int rn = wn * 32 + nt * 8 + g;
        b[0] = ldsu(&Bs[rn * 36 + k * 8 + tig]);
        b[1] = ldsu(&Bs[rn * 36 + k * 8 + tig + 4]);
        mma8(C[0][nt], a[0], b);
        mma8(C[1][nt], a[1], b);
      }
    }
  }
  #pragma unroll
  for (int mt = 0; mt < 2; mt++) {
    int r = m0 + wm * 32 + mt * 16 + g;
    #pragma unroll
    for (int nt = 0; nt < 4; nt++) {
      int c = n0 + wn * 32 + nt * 8 + 2 * tig;
      if (c < DD) {
        float b0 = bias[c], b1 = bias[c + 1];
        *(float2*)&g_t[(size_t)r * DD + c] =
            make_float2(C[mt][nt][0] + b0, C[mt][nt][1] + b1);
        *(float2*)&g_t[(size_t)(r + 8) * DD + c] =
            make_float2(C[mt][nt][2] + b0, C[mt][nt][3] + b1);
      }
    }
  }
}

// ---------------- kernels 5/6: BN column stats -----------------------------------
__global__ void __launch_bounds__(256) colstat_part_kernel() {
  int p = blockIdx.x;
  const float* base = g_t + (size_t)p * 64 * DD;
  int c = threadIdx.x;
  float s0 = 0.f, q0 = 0.f, s1 = 0.f, q1 = 0.f;
  for (int r = 0; r < 64; r++) {
    float v0 = base[r * DD + c]; s0 += v0; q0 += v0 * v0;
    if (c + 256 < DD) { float v1 = base[r * DD + c + 256]; s1 += v1; q1 += v1 * v1; }
  }
  g_part[p * DD + c] = s0; g_partq[p * DD + c] = q0;
  if (c + 256 < DD) { g_part[p * DD + c + 256] = s1; g_partq[p * DD + c + 256] = q1; }
}

__global__ void colstat_final_kernel() {
  int c = blockIdx.x * 256 + threadIdx.x;
  if (c >= DD) return;
  float s = 0.f, q = 0.f;
  for (int i = 0; i < 128; i++) { s += g_part[i * DD + c]; q += g_partq[i * DD + c]; }
  float mu = s * (1.f / NROWS);
  float var = q * (1.f / NROWS) - mu * mu;
  g_mu[c] = mu;
  g_rs[c] = rsqrtf(var + 1e-5f);
}

// ---------------- kernel 7: BN apply + ReLU + residual ---------------------------
__global__ void __launch_bounds__(256) bn_apply_kernel(
    const float* __restrict__ g, const float* __restrict__ b, int layer,
    float* __restrict__ out_ext) {
  int idx = blockIdx.x * 256 + threadIdx.x;
  if (idx >= NELEM) return;
  const float* res = layer ? g_out2 : g_out1;
  float* outp = layer ? out_ext : g_out2;
  int c = idx % DD;
  float v = (g_t[idx] - g_mu[c]) * g_rs[c] * g[c] + b[c];
  outp[idx] = res[idx] + fmaxf(v, 0.f);
}

// ---------------- launch ----------------------------------------------------------
extern "C" void kernel_launch(void* const* d_in, const int* in_sizes, int n_in,
                              void* d_out, int out_size) {
  (void)in_sizes; (void)n_in; (void)out_size;
  const float* x    = (const float*)d_in[0];
  const float* ln1g = (const float*)d_in[1];
  const float* ln1b = (const float*)d_in[2];
  const float* Wq   = (const float*)d_in[3];
  const float* bq   = (const float*)d_in[4];
  const float* Wk   = (const float*)d_in[5];
  const float* bk   = (const float*)d_in[6];
  const float* Wv   = (const float*)d_in[7];
  const float* bv   = (const float*)d_in[8];
  const float* ln2g = (const float*)d_in[9];
  const float* ln2b = (const float*)d_in[10];
  const float* W1   = (const float*)d_in[11];
  const float* b1   = (const float*)d_in[12];
  const float* bn1g = (const float*)d_in[13];
  const float* bn1b = (const float*)d_in[14];
  const float* W2   = (const float*)d_in[15];
  const float* b2   = (const float*)d_in[16];
  const float* bn2g = (const float*)d_in[17];
  const float* bn2b = (const float*)d_in[18];
  float* out = (float*)d_out;

  cudaFuncSetAttribute(attn_mma_kernel, cudaFuncAttributeMaxDynamicSharedMemorySize,
                       ATT_SMEM);

  ln1_qkv_kernel<<<NROWS / 8, 256>>>(x, ln1g, ln1b, Wq, bq, Wk, bk, Wv, bv);
  attn_mma_kernel<<<dim3(SS / 128, BB * HH), 128, ATT_SMEM>>>(x);
  ln2_kernel<<<NROWS, 256>>>(ln2g, ln2b);
  gemm_mma_kernel<<<dim3(NROWS / 128, 8), 256>>>(W1, b1, 0);
  colstat_part_kernel<<<128, 256>>>();
  colstat_final_kernel<<<2, 256>>>();
  bn_apply_kernel<<<(NELEM + 255) / 256, 256>>>(bn1g, bn1b, 0, out);
  gemm_mma_kernel<<<dim3(NROWS / 128, 8), 256>>>(W2, b2, 1);
  colstat_part_kernel<<<128, 256>>>();
  colstat_final_kernel<<<2, 256>>>();
  bn_apply_kernel<<<(NELEM + 255) / 256, 256>>>(bn2g, bn2b, 1, out);
}